// round 16
// baseline (speedup 1.0000x reference)
#include <cuda_runtime.h>
#include <cuda_bf16.h>

#define SENSOR   256
#define IMG_W    1024
#define IMG_H    1024
#define SPP      16
#define NCH      3
#define NBATCH   4
#define HW       (IMG_H * IMG_W)

// warp = 8 adjacent sensor px  x  4 spp-groups; each thread runs 4 spp.
// lane = (g<<3) | q

__device__ __forceinline__ float ftanh(float x) {
    float e = __expf(2.0f * x);
    return 1.0f - __fdividef(2.0f, e + 1.0f);
}

__global__ __launch_bounds__(128, 10)
void foveated_sensor_kernel(const float* __restrict__ img,
                            const float* __restrict__ t,
                            const float* __restrict__ jitter,
                            float* __restrict__ out)
{
    const int lane = threadIdx.x & 31;
    const int q    = lane & 7;
    const int g    = lane >> 3;
    const int gw   = blockIdx.x * 4 + (threadIdx.x >> 5);
    const int p    = (gw << 3) + q;          // sensor pixel
    const int b    = blockIdx.y;

    const int sw = p & (SENSOR - 1);
    const int sh = p >> 8;

    const float step = 2.0f / (float)SENSOR;
    const float pxv = -1.0f + (float)sw * step;
    const float pyv = -1.0f + (float)sh * step;

    const float tt    = __ldg(t);
    const float s     = tanhf(tt);
    const float inv_s = 1.0f / s;
    const float A     = inv_s * 512.0f;      // gx = thx*A + 511.5
    const float C     = tt * inv_s;          // ddx = C - C*thx^2

    const float* __restrict__ imgb = img + (size_t)b * NCH * HW;
    const float2* __restrict__ jit = (const float2*)jitter;

    // hoist all 4 jitter loads (independent, deep MLP)
    const int kbase = g << 2;
    float2 j0 = __ldg(&jit[((kbase + 0) << 16) + p]);
    float2 j1 = __ldg(&jit[((kbase + 1) << 16) + p]);
    float2 j2 = __ldg(&jit[((kbase + 2) << 16) + p]);
    float2 j3 = __ldg(&jit[((kbase + 3) << 16) + p]);

    float acc0 = 0.f, acc1 = 0.f, acc2 = 0.f, dsum = 0.f;

#pragma unroll
    for (int kk = 0; kk < 4; ++kk) {
        float2 j = (kk == 0) ? j0 : (kk == 1) ? j1 : (kk == 2) ? j2 : j3;
        float posx = fmaf(j.x, step, pxv);
        float posy = fmaf(j.y, step, pyv);

        float thx = ftanh(tt * posx);
        float thy = ftanh(tt * posy);

        float ddx = fmaf(-C, thx * thx, C);
        float ddy = fmaf(-C, thy * thy, C);
        float det = ddx * ddy;
        dsum += det;

        float gx = fmaf(thx, A, 511.5f);
        float gy = fmaf(thy, A, 511.5f);
        gx = fminf(fmaxf(gx, 0.0f), (float)(IMG_W - 1));
        gy = fminf(fmaxf(gy, 0.0f), (float)(IMG_H - 1));

        float x0f = floorf(gx);
        float y0f = floorf(gy);
        float wx = gx - x0f;
        float wy = gy - y0f;

        int x0 = (int)x0f;
        int y0 = (int)y0f;
        int x1 = min(x0 + 1, IMG_W - 1);
        int y1 = min(y0 + 1, IMG_H - 1);

        const int o00 = (y0 << 10) + x0;
        const int o01 = (y0 << 10) + x1;
        const int o10 = (y1 << 10) + x0;
        const int o11 = (y1 << 10) + x1;

        float a00 = __ldg(imgb + o00);
        float a01 = __ldg(imgb + o01);
        float a10 = __ldg(imgb + o10);
        float a11 = __ldg(imgb + o11);
        const float* ip1 = imgb + HW;
        float b00 = __ldg(ip1 + o00);
        float b01 = __ldg(ip1 + o01);
        float b10 = __ldg(ip1 + o10);
        float b11 = __ldg(ip1 + o11);
        const float* ip2 = imgb + 2 * HW;
        float c00 = __ldg(ip2 + o00);
        float c01 = __ldg(ip2 + o01);
        float c10 = __ldg(ip2 + o10);
        float c11 = __ldg(ip2 + o11);

        float top, bot;
        top = fmaf(wx, a01 - a00, a00); bot = fmaf(wx, a11 - a10, a10);
        acc0 = fmaf(fmaf(wy, bot - top, top), det, acc0);
        top = fmaf(wx, b01 - b00, b00); bot = fmaf(wx, b11 - b10, b10);
        acc1 = fmaf(fmaf(wy, bot - top, top), det, acc1);
        top = fmaf(wx, c01 - c00, c00); bot = fmaf(wx, c11 - c10, c10);
        acc2 = fmaf(fmaf(wy, bot - top, top), det, acc2);
    }

    // reduce across the 4 spp-groups (xor 8, 16)
    acc0 += __shfl_xor_sync(0xffffffffu, acc0, 8);
    acc1 += __shfl_xor_sync(0xffffffffu, acc1, 8);
    acc2 += __shfl_xor_sync(0xffffffffu, acc2, 8);
    dsum += __shfl_xor_sync(0xffffffffu, dsum, 8);

    acc0 += __shfl_xor_sync(0xffffffffu, acc0, 16);
    acc1 += __shfl_xor_sync(0xffffffffu, acc1, 16);
    acc2 += __shfl_xor_sync(0xffffffffu, acc2, 16);
    dsum += __shfl_xor_sync(0xffffffffu, dsum, 16);

    if (lane < 8) {
        const float invd = 1.0f / dsum;
        out[((b * NCH + 0) << 16) + p] = acc0 * invd;
        out[((b * NCH + 1) << 16) + p] = acc1 * invd;
        out[((b * NCH + 2) << 16) + p] = acc2 * invd;
    }
}

extern "C" void kernel_launch(void* const* d_in, const int* in_sizes, int n_in,
                              void* d_out, int out_size)
{
    const float* img    = (const float*)d_in[0];
    const float* t      = (const float*)d_in[1];
    const float* jitter = (const float*)d_in[2];
    float* out          = (float*)d_out;

    // 8 px/warp, 4 warps/block -> 32 px per block
    dim3 grid(SENSOR * SENSOR / 32, NBATCH);
    foveated_sensor_kernel<<<grid, 128>>>(img, t, jitter, out);
}